// round 13
// baseline (speedup 1.0000x reference)
#include <cuda_runtime.h>
#include <stdint.h>

// RadialTokenizer — octet-span gather (8 px per L1 line-wavefront).
// bin = floor((x*0.5+0.5)*255)-127 in [0,127]; 16 rings: mean/std/median
// from exact per-ring 128-bin histograms.
// Entry = (octet<<8)|mask : octet = 8 aligned px of one row, mask = which of
// the 8 px belong to this ring (<=2 rings per octet since |grad d|<=1).
// Warp = ring pair (p, 15-p): identical work. Per-lane byte histograms
// (bank==lane, conflict-free, no atomics), chunked so counters never
// overflow; exact counting via masks (no sentinels, no padding fixups).

#define HH 256
#define WW 256
#define NR 16
#define NOCT 8192          // 256 rows x 32 octets
#define ESTRIDE 2048       // max entries/ring ~1.3K

__device__ int g_ecnt[NR];
__device__ uint32_t g_ent[NR * ESTRIDE];

// ring i <=> 64*i^2 < d2 <= 64*(i+1)^2 ; center pixel excluded. Exact
// (float seed + integer fixup).
__device__ __forceinline__ int ring_of(int x, int y) {
    int dx = x - 128, dy = y - 128;
    int d2 = dx * dx + dy * dy;
    if (d2 == 0 || d2 > 16384) return -1;
    int i = (int)(__fmul_rn(sqrtf((float)d2), 0.125f) + 0.999f) - 1;
    if (i < 0) i = 0;
    while (i > 0 && 64 * i * i >= d2) i--;
    while (d2 > 64 * (i + 1) * (i + 1)) i++;
    return i;
}

// ---------------- init kernels (deterministic, every launch) ----------------

__global__ void k_zero() {
    if (threadIdx.x < NR) g_ecnt[threadIdx.x] = 0;
}

// one thread per octet: classify 8 px, emit <=2 (ring, mask) entries.
__global__ void k_build() {
    int oct = blockIdx.x * 256 + threadIdx.x;   // 32 blocks
    int y  = oct >> 5;
    int x0 = (oct & 31) << 3;
    int r1 = -1, r2 = -1, m1 = 0, m2 = 0;
    #pragma unroll
    for (int j = 0; j < 8; j++) {
        int r = ring_of(x0 + j, y);
        if (r >= 0) {
            if (r1 < 0 || r == r1)      { r1 = r; m1 |= 1 << j; }
            else                        { r2 = r; m2 |= 1 << j; }
        }
    }
    if (r1 >= 0) {
        int pos = atomicAdd(&g_ecnt[r1], 1);
        g_ent[r1 * ESTRIDE + pos] = ((uint32_t)oct << 8) | (uint32_t)m1;
    }
    if (r2 >= 0) {
        int pos = atomicAdd(&g_ecnt[r2], 1);
        g_ent[r2 * ESTRIDE + pos] = ((uint32_t)oct << 8) | (uint32_t)m2;
    }
}

// ---------------- main kernel ----------------
// Grid 1536 = (bc=768) x 2 halves; block 128 (4 warps, 16KB smem).
// Warp w -> rings p, 15-p with p = (bx&1)*4 + w.
// Hist byte addr = ((bin<<5)&0xF80) | (lane<<2) | (bin&3)  -> bank == lane.

__global__ void __launch_bounds__(128, 10) k_main(const float* __restrict__ img,
                                                  float* __restrict__ out) {
    __shared__ uint8_t hist[4][4096];

    const int lane = threadIdx.x & 31;
    const int w    = threadIdx.x >> 5;
    const int bc   = blockIdx.x >> 1;
    const int p    = ((blockIdx.x & 1) << 2) + w;   // 0..7

    uint8_t* h = hist[w];
    const float* __restrict__ ip = img + (size_t)bc * (HH * WW);
    const float4* __restrict__ ip4 = (const float4*)ip;
    const int hb_lane = lane << 2;
    const int b = bc / 3, c = bc - b * 3;

    #pragma unroll
    for (int rr = 0; rr < 2; rr++) {
        const int ring = rr ? (15 - p) : p;
        const int cnt  = g_ecnt[ring];
        const uint32_t* __restrict__ lst = g_ent + ring * ESTRIDE;
        const int steps = (cnt + 31) >> 5;

        int H0 = 0, H1 = 0, H2 = 0, H3 = 0;

        // chunks of <=31 steps: per-lane per-bin count <= 31*8 = 248 < 255
        for (int s0 = 0; s0 < steps; s0 += 31) {
            const int se = (s0 + 31 < steps) ? (s0 + 31) : steps;

            // zero this warp's 4KB histogram
            {
                uint4* hz = (uint4*)h;
                uint4 z; z.x = z.y = z.z = z.w = 0u;
                #pragma unroll
                for (int j = 0; j < 8; j++) hz[j * 32 + lane] = z;
            }
            __syncwarp();

            #pragma unroll 4
            for (int s = s0; s < se; s++) {
                int i = (s << 5) + lane;
                uint32_t e = (i < cnt) ? lst[i] : 0u;   // mask 0 -> no-op
                uint32_t oct = e >> 8;
                float4 a  = __ldcs(ip4 + (oct << 1));
                float4 bq = __ldcs(ip4 + (oct << 1) + 1);
                float xv[8] = {a.x, a.y, a.z, a.w, bq.x, bq.y, bq.z, bq.w};
                #pragma unroll
                for (int j = 0; j < 8; j++) {
                    // bit-identical to ref: fma(x,0.5,0.5) (exact mul ->
                    // single rounding == (x*0.5)+0.5), unfused *255, floor.
                    float t = __fmul_rn(__fmaf_rn(xv[j], 0.5f, 0.5f), 255.0f);
                    int bin = __float2int_rd(t) - 127;
                    if (e & (1u << j))
                        h[((bin << 5) & 0xF80) | hb_lane | (bin & 3)] += 1;
                }
            }
            __syncwarp();

            // reduce chunk: lane l owns bins 4l..4l+3
            const uint32_t* hw = (const uint32_t*)h;
            uint32_t a02 = 0, a13 = 0;
            #pragma unroll
            for (int jj = 0; jj < 32; jj++) {
                int j = (jj + lane) & 31;
                uint32_t vv = hw[lane * 32 + j];
                a02 += vv & 0x00FF00FFu;
                a13 += (vv >> 8) & 0x00FF00FFu;
            }
            H0 += (int)(a02 & 0xFFFFu);
            H2 += (int)(a02 >> 16);
            H1 += (int)(a13 & 0xFFFFu);
            H3 += (int)(a13 >> 16);
            __syncwarp();   // reads done before next chunk's rezero
        }

        // ---- stats from the exact histogram ----
        const int b0 = lane * 4;
        int sl  = H0 + H1 + H2 + H3;
        int sb  = H0 * b0 + H1 * (b0 + 1) + H2 * (b0 + 2) + H3 * (b0 + 3);
        int sb2 = H0 * b0 * b0 + H1 * (b0 + 1) * (b0 + 1)
                + H2 * (b0 + 2) * (b0 + 2) + H3 * (b0 + 3) * (b0 + 3);

        int sumb  = __reduce_add_sync(0xffffffffu, sb);
        int sumb2 = __reduce_add_sync(0xffffffffu, sb2);

        int sc = sl;
        #pragma unroll
        for (int d = 1; d < 32; d <<= 1) {
            int t2 = __shfl_up_sync(0xffffffffu, sc, d);
            if (lane >= d) sc += t2;
        }
        const int n  = __shfl_sync(0xffffffffu, sc, 31);
        const int cb = sc - sl;

        int k1 = (n - 1) >> 1, k2 = n >> 1;
        int c1 = 1 << 30, c2 = 1 << 30;
        {
            int t1 = k1 + 1;
            if (cb < t1 && t1 <= sc) {
                if      (cb + H0 >= t1)           c1 = b0;
                else if (cb + H0 + H1 >= t1)      c1 = b0 + 1;
                else if (cb + H0 + H1 + H2 >= t1) c1 = b0 + 2;
                else                              c1 = b0 + 3;
            }
            int t2r = k2 + 1;
            if (cb < t2r && t2r <= sc) {
                if      (cb + H0 >= t2r)           c2 = b0;
                else if (cb + H0 + H1 >= t2r)      c2 = b0 + 1;
                else if (cb + H0 + H1 + H2 >= t2r) c2 = b0 + 2;
                else                               c2 = b0 + 3;
            }
        }
        int m1 = __reduce_min_sync(0xffffffffu, c1);
        int m2 = __reduce_min_sync(0xffffffffu, c2);

        if (lane == 0) {
            double dn = (double)n;
            double mb = (double)sumb / dn;
            double mean = 127.0 + mb;
            double var = (double)sumb2 / dn - mb * mb;
            double sd = sqrt(var > 0.0 ? var : 0.0);
            double med = 127.0 + 0.5 * (double)(m1 + m2);
            int o = b * (NR * 9) + ring * 9 + c;
            out[o]     = (float)mean;
            out[o + 3] = (float)sd;
            out[o + 6] = (float)med;
        }
        __syncwarp();
    }
}

extern "C" void kernel_launch(void* const* d_in, const int* in_sizes, int n_in,
                              void* d_out, int out_size) {
    const float* img = (const float*)d_in[0];
    float* out = (float*)d_out;

    k_zero<<<1, 32>>>();
    k_build<<<32, 256>>>();
    k_main<<<1536, 128>>>(img, out);
}

// round 14
// speedup vs baseline: 1.5714x; 1.5714x over previous
#include <cuda_runtime.h>
#include <stdint.h>

// RadialTokenizer — direct gather (R4 family) + single-kernel init +
// software-pipelined offset loads.
// bin = floor((x*0.5+0.5)*255)-127 in [0,127]; 16 rings: mean/std/median
// from exact per-ring 128-bin histograms.
// Warp = ring pair (p, 15-p): identical work per warp. Per-lane byte
// histograms (bank==lane, conflict-free, no atomics).

#define HH 256
#define WW 256
#define NR 16
#define RSTRIDE 8192     // slots per ring; max ring population ~6233

__device__ __align__(128) uint16_t g_off[NR * RSTRIDE];
__device__ int g_n[NR];   // final ring counts (non-atomic, written by k_build)

// ring i <=> 64*i^2 < d2 <= 64*(i+1)^2 ; center pixel excluded. Exact
// (float seed + integer fixup).
__device__ __forceinline__ int ring_of(int x, int y) {
    int dx = x - 128, dy = y - 128;
    int d2 = dx * dx + dy * dy;
    if (d2 == 0 || d2 > 16384) return -1;
    int i = (int)(__fmul_rn(sqrtf((float)d2), 0.125f) + 0.999f) - 1;
    if (i < 0) i = 0;
    while (i > 0 && 64 * i * i >= d2) i--;
    while (d2 > 64 * (i + 1) * (i + 1)) i++;
    return i;
}

// ---------------- single init kernel: <<<1, 1024>>> ----------------
// Block-local smem cursors (no global state to re-zero across graph
// replays). Warp-aggregated: one atomic per (warp, ring) group. Within a
// warp, px are consecutive x of one row -> consecutive ranks -> span-
// coalesced list entries.

__global__ void k_build() {
    __shared__ int cur[NR];
    const int tid  = threadIdx.x;
    const int lane = tid & 31;
    const unsigned lt = (1u << lane) - 1u;
    if (tid < NR) cur[tid] = 0;
    __syncthreads();

    for (int it = 0; it < 64; it++) {
        int px = it * 1024 + tid;
        int x = px & 255, y = px >> 8;
        int r = ring_of(x, y);
        unsigned m = __match_any_sync(0xffffffffu, r);
        int rank = __popc(m & lt);
        int base = 0;
        if (r >= 0 && rank == 0)
            base = atomicAdd(&cur[r], __popc(m));
        int ldr = __ffs(m) - 1;
        base = __shfl_sync(0xffffffffu, base, ldr);
        if (r >= 0)
            g_off[r * RSTRIDE + base + rank] = (uint16_t)((y << 8) | x);
    }
    __syncthreads();
    if (tid < NR) g_n[tid] = cur[tid];
}

// ---------------- main kernel ----------------
// Grid 1536 = (bc=768) x 2 halves; block 128 (4 warps, 16KB smem, 8
// blocks/SM target). Warp w -> rings p, 15-p with p = (bx&1)*4 + w.
// Hist byte addr = ((bin<<5)&0xF80) | (lane<<2) | (bin&3)  -> bank == lane.
// Offset loads for block i+1 are prefetched while block i's gathers fly.

__global__ void __launch_bounds__(128, 8) k_main(const float* __restrict__ img,
                                                 float* __restrict__ out) {
    __shared__ uint8_t hist[4][4096];

    const int lane = threadIdx.x & 31;
    const int w    = threadIdx.x >> 5;
    const int bc   = blockIdx.x >> 1;
    const int p    = ((blockIdx.x & 1) << 2) + w;   // pair index 0..7

    uint8_t* h = hist[w];
    const float* __restrict__ ip = img + (size_t)bc * (HH * WW);
    const int hb_lane = lane << 2;
    const int b = bc / 3, c = bc - b * 3;

    #pragma unroll
    for (int rr = 0; rr < 2; rr++) {
        const int ring = rr ? (15 - p) : p;

        // zero this warp's 4KB histogram
        {
            uint4* hz = (uint4*)h;
            uint4 z; z.x = z.y = z.z = z.w = 0u;
            #pragma unroll
            for (int j = 0; j < 8; j++) hz[j * 32 + lane] = z;
        }
        __syncwarp();

        const int n = g_n[ring];
        const uint16_t* __restrict__ offs = g_off + ring * RSTRIDE;
        const uint32_t* __restrict__ o32 = (const uint32_t*)offs;

        // ---- pipelined main loop: 256 px/step, MLP=8 gathers, next step's
        // offsets prefetched during current gathers ----
        const int nfull = n & ~255;
        uint32_t ow[4];
        #pragma unroll
        for (int j = 0; j < 4; j++)
            ow[j] = (nfull > 0) ? o32[j * 32 + lane] : 0u;

        for (int base = 0; base < nfull; base += 256) {
            float v[8];
            #pragma unroll
            for (int j = 0; j < 4; j++) {
                v[2 * j]     = __ldcs(ip + (ow[j] & 0xFFFFu));
                v[2 * j + 1] = __ldcs(ip + (ow[j] >> 16));
            }
            uint32_t nw[4];
            const int nb = base + 256;
            #pragma unroll
            for (int j = 0; j < 4; j++)
                nw[j] = (nb < nfull) ? o32[(nb >> 1) + j * 32 + lane] : 0u;
            #pragma unroll
            for (int j = 0; j < 8; j++) {
                // bit-identical to ref: fma(x,0.5,0.5) (exact mul -> single
                // rounding == (x*0.5)+0.5), then unfused *255, then floor.
                float t = __fmul_rn(__fmaf_rn(v[j], 0.5f, 0.5f), 255.0f);
                int bin = __float2int_rd(t) - 127;
                h[((bin << 5) & 0xF80) | hb_lane | (bin & 3)] += 1;
            }
            #pragma unroll
            for (int j = 0; j < 4; j++) ow[j] = nw[j];
        }
        // tail (< 256 px)
        for (int i = nfull + lane; i < n; i += 32) {
            int off = offs[i];
            float t = __fmul_rn(__fmaf_rn(__ldcs(ip + off), 0.5f, 0.5f), 255.0f);
            int bin = __float2int_rd(t) - 127;
            h[((bin << 5) & 0xF80) | hb_lane | (bin & 3)] += 1;
        }
        __syncwarp();

        // ---- reduce: lane l owns bins 4l..4l+3; sum byte cols of 32 lanes ----
        const uint32_t* hw = (const uint32_t*)h;
        uint32_t a02 = 0, a13 = 0;
        #pragma unroll
        for (int jj = 0; jj < 32; jj++) {
            int j = (jj + lane) & 31;
            uint32_t vv = hw[lane * 32 + j];
            a02 += vv & 0x00FF00FFu;
            a13 += (vv >> 8) & 0x00FF00FFu;
        }
        int h0 = (int)(a02 & 0xFFFFu), h2 = (int)(a02 >> 16);
        int h1 = (int)(a13 & 0xFFFFu), h3 = (int)(a13 >> 16);

        const int b0 = lane * 4;
        int sl  = h0 + h1 + h2 + h3;
        int sb  = h0 * b0 + h1 * (b0 + 1) + h2 * (b0 + 2) + h3 * (b0 + 3);
        int sb2 = h0 * b0 * b0 + h1 * (b0 + 1) * (b0 + 1)
                + h2 * (b0 + 2) * (b0 + 2) + h3 * (b0 + 3) * (b0 + 3);

        int sumb  = __reduce_add_sync(0xffffffffu, sb);
        int sumb2 = __reduce_add_sync(0xffffffffu, sb2);

        int sc = sl;
        #pragma unroll
        for (int d = 1; d < 32; d <<= 1) {
            int t2 = __shfl_up_sync(0xffffffffu, sc, d);
            if (lane >= d) sc += t2;
        }
        int cb = sc - sl;

        int k1 = (n - 1) >> 1, k2 = n >> 1;
        int c1 = 1 << 30, c2 = 1 << 30;
        {
            int t1 = k1 + 1;
            if (cb < t1 && t1 <= sc) {
                if      (cb + h0 >= t1)           c1 = b0;
                else if (cb + h0 + h1 >= t1)      c1 = b0 + 1;
                else if (cb + h0 + h1 + h2 >= t1) c1 = b0 + 2;
                else                              c1 = b0 + 3;
            }
            int t2r = k2 + 1;
            if (cb < t2r && t2r <= sc) {
                if      (cb + h0 >= t2r)           c2 = b0;
                else if (cb + h0 + h1 >= t2r)      c2 = b0 + 1;
                else if (cb + h0 + h1 + h2 >= t2r) c2 = b0 + 2;
                else                               c2 = b0 + 3;
            }
        }
        int m1 = __reduce_min_sync(0xffffffffu, c1);
        int m2 = __reduce_min_sync(0xffffffffu, c2);

        if (lane == 0) {
            double dn = (double)n;
            double mb = (double)sumb / dn;
            double mean = 127.0 + mb;
            double var = (double)sumb2 / dn - mb * mb;
            double sd = sqrt(var > 0.0 ? var : 0.0);
            double med = 127.0 + 0.5 * (double)(m1 + m2);
            int o = b * (NR * 9) + ring * 9 + c;
            out[o]     = (float)mean;
            out[o + 3] = (float)sd;
            out[o + 6] = (float)med;
        }
        __syncwarp();
    }
}

extern "C" void kernel_launch(void* const* d_in, const int* in_sizes, int n_in,
                              void* d_out, int out_size) {
    const float* img = (const float*)d_in[0];
    float* out = (float*)d_out;

    k_build<<<1, 1024>>>();
    k_main<<<1536, 128>>>(img, out);
}